// round 5
// baseline (speedup 1.0000x reference)
#include <cuda_runtime.h>
#include <cstdint>

#define N_STFT   1025
#define N_MELS   128
#define BATCH    4
#define TIME     1024
#define ROWS     (BATCH*TIME)
#define MAX_ITER 20
#define LR       0.3f
#define MOM      0.9f
#define INVC     (2.0f/4096.0f)
#define CH       33            // frequency bins per lane (32*33 = 1056 >= 1025)
#define WPB      4             // warps (rows) per CTA
#define FPAD     (32*CH)       // 1056

// ---------------- device globals ----------------
__device__ float2        g_w01[FPAD];     // (w0,w1) per frequency, zero tail
__device__ unsigned char g_mbt[N_STFT];   // first-nonzero mel per frequency

// ---------------- table build: one warp per frequency ----------------
__global__ void build_tables_k(const float* __restrict__ fb) {
    int gw   = (blockIdx.x * blockDim.x + threadIdx.x) >> 5;
    int lane = threadIdx.x & 31;
    if (gw >= FPAD) return;
    if (gw >= N_STFT) { if (!lane) g_w01[gw] = make_float2(0.f, 0.f); return; }
    const float* r = fb + (size_t)gw * N_MELS;
    int m4 = lane * 4;
    unsigned loc = 128u;
    #pragma unroll
    for (int k = 3; k >= 0; k--) if (r[m4 + k] != 0.f) loc = (unsigned)(m4 + k);
    #pragma unroll
    for (int o = 16; o; o >>= 1) {
        unsigned v = __shfl_xor_sync(0xffffffffu, loc, o);
        loc = v < loc ? v : loc;
    }
    if (!lane) {
        float w0 = 0.f, w1 = 0.f; int mm = 0;
        if (loc < 128u) {
            mm = (int)loc;
            w0 = r[loc];
            w1 = (loc < 127u) ? r[loc + 1] : 0.f;
        }
        g_w01[gw] = make_float2(w0, w1);
        g_mbt[gw] = (unsigned char)mm;
    }
}

// ---------------- asm helpers ----------------
__device__ __forceinline__ unsigned smaddr(const void* p) {
    return (unsigned)__cvta_generic_to_shared(p);
}
__device__ __forceinline__ void sts_f32(unsigned a, float v) {
    asm volatile("st.shared.f32 [%0], %1;" :: "r"(a), "f"(v) : "memory");
}
__device__ __forceinline__ float lds_f32(unsigned a) {
    float v; asm volatile("ld.shared.f32 %0, [%1];" : "=f"(v) : "r"(a)); return v;
}

// Per-bin control: one setp from sign(w0), shared by all predicated ops.
// Flush a0 -> slot0 of completed mel; shift (a0<-a1, a1<-0); advance acc/diff
// cursors; shift d0<-d1; load next diff only on mel change.
#define CTRL_FULL(w0i) asm volatile(                     \
    "{\n\t.reg .pred p;\n\t"                             \
    "setp.lt.f32 p, %6, 0f00000000;\n\t"                 \
    "@p st.shared.f32 [%0], %2;\n\t"                     \
    "selp.f32 %2, %3, %2, p;\n\t"                        \
    "selp.f32 %3, 0f00000000, %3, p;\n\t"                \
    "@p add.u32 %0, %0, 16;\n\t"                         \
    "selp.f32 %4, %5, %4, p;\n\t"                        \
    "@p ld.shared.f32 %5, [%1+8];\n\t"                   \
    "@p add.u32 %1, %1, 4;\n\t}"                         \
    : "+r"(aaddr), "+r"(daddr), "+f"(a0), "+f"(a1),      \
      "+f"(d0), "+f"(d1)                                 \
    : "f"(w0i) : "memory")

// forward-only variant (prologue)
#define CTRL_FWD(w0i) asm volatile(                      \
    "{\n\t.reg .pred p;\n\t"                             \
    "setp.lt.f32 p, %3, 0f00000000;\n\t"                 \
    "@p st.shared.f32 [%0], %1;\n\t"                     \
    "selp.f32 %1, %2, %1, p;\n\t"                        \
    "selp.f32 %2, 0f00000000, %2, p;\n\t"                \
    "@p add.u32 %0, %0, 16;\n\t}"                        \
    : "+r"(aaddr), "+f"(a0), "+f"(a1)                    \
    : "f"(w0i) : "memory")

// ---------------- shared: iteration phase / epilogue stage union ----------------
struct __align__(16) SmemIter {
    float acc[WPB][132][4];    // 4 statically collision-free slots per mel
    float diff[WPB][132];      // e[m] (+ zero pads 128..131)
};
union __align__(16) SmemU {
    SmemIter it;
    float    stage[WPB][FPAD];
};

// ---------------- main: warp = one (b,t) row; 20 fused iterations ----------------
__global__ void __launch_bounds__(WPB*32, 3)
imel_k(const float* __restrict__ mel, const float* __restrict__ spi,
       float* __restrict__ out)
{
    __shared__ SmemU S;
    const int tid  = threadIdx.x;
    const int wid  = tid >> 5;
    const int lane = tid & 31;
    const int row  = blockIdx.x * WPB + wid;
    const int b    = row >> 10;
    const int t    = row & (TIME - 1);

    // one-time zero of acc slots (write pattern static across iters) + diff pads
    {
        float4 z = make_float4(0.f, 0.f, 0.f, 0.f);
        for (int k = lane; k < 132; k += 32)
            *reinterpret_cast<float4*>(&S.it.acc[wid][k][0]) = z;
        if (lane < 4) S.it.diff[wid][128 + lane] = 0.f;
    }

    const int f_lo = lane * CH;

    // register-resident state: weights (sign of w0 = "mel changes at this bin"),
    // spectrogram estimate, momentum buffer
    float w0[CH], w1[CH], sp[CH], bu[CH];
    int mfirst;
    {
        int pm = 0;
        #pragma unroll
        for (int i = 0; i < CH; i++) {
            int f  = f_lo + i;
            int fc = f > N_STFT-1 ? N_STFT-1 : f;
            float2 w = g_w01[f];                 // zero tail beyond N_STFT
            sp[i] = spi[(size_t)row * N_STFT + fc];
            bu[i] = 0.f;
            int m = (int)g_mbt[fc];
            if (i == 0) { mfirst = m; pm = m; w0[0] = w.x; }
            else {
                m = m < pm ? pm : m;             // monotone clamp (zero rows/pads)
                w0[i] = (m != pm) ? -w.x : w.x;  // sign bit = change flag
                pm = m;
            }
            w1[i] = w.y;
        }
    }
    float melI[4];
    #pragma unroll
    for (int j = 0; j < 4; j++)
        melI[j] = mel[(size_t)b*(N_MELS*TIME) + (size_t)(lane + 32*j)*TIME + t] * INVC;

    __syncwarp();   // zeroed acc visible before cross-lane flushes

    const unsigned accb  = smaddr(&S.it.acc[wid][0][0]);
    const unsigned diffb = smaddr(&S.it.diff[wid][0]);
    // end-flush slots: lanes 0..30 -> slot1 (mlast) / slot2 (mlast+1); lane31 -> slot3
    const unsigned eo0 = (lane == 31) ? 12u : 4u;
    const unsigned eo1 = (lane == 31) ? 28u : 24u;

    // ---- prologue forward: scatter proj of iteration 0 ----
    {
        unsigned aaddr = accb + (unsigned)mfirst * 16u;
        float a0 = 0.f, a1 = 0.f;
        #pragma unroll
        for (int i = 0; i < CH; i++) {
            if (i > 0) CTRL_FWD(w0[i]);
            float aw = fabsf(w0[i]);
            a0 = fmaf(sp[i], aw,    a0);
            a1 = fmaf(sp[i], w1[i], a1);
        }
        sts_f32(aaddr + eo0, a0);
        sts_f32(aaddr + eo1, a1);
    }
    __syncwarp();

    #pragma unroll 1
    for (int it = 0; it < MAX_ITER; it++) {
        // ---- combine: e[m] = INVC*proj[m] - INVC*mel[m] ----
        #pragma unroll
        for (int j = 0; j < 4; j++) {
            int m = lane + 32*j;
            float4 v = *reinterpret_cast<const float4*>(&S.it.acc[wid][m][0]);
            float s = (v.x + v.y) + (v.z + v.w);
            sts_f32(diffb + (unsigned)m * 4u, fmaf(s, INVC, -melI[j]));
        }
        __syncwarp();

        // ---- fused backward(it) + forward(it+1) ----
        unsigned aaddr = accb + (unsigned)mfirst * 16u;
        unsigned daddr = diffb + (unsigned)mfirst * 4u;
        float d0 = lds_f32(daddr);
        float d1 = lds_f32(daddr + 4u);
        float a0 = 0.f, a1 = 0.f;
        #pragma unroll
        for (int i = 0; i < CH; i++) {
            if (i > 0) CTRL_FULL(w0[i]);
            float aw = fabsf(w0[i]);
            float g  = fmaf(d1, w1[i], d0 * aw);      // grad_f = e[m]*w0 + e[m+1]*w1
            bu[i] = fmaf(MOM, bu[i], g);
            sp[i] = fmaxf(fmaf(-LR, bu[i], sp[i]), 0.f);
            a0 = fmaf(sp[i], aw,    a0);              // forward for next iteration
            a1 = fmaf(sp[i], w1[i], a1);
        }
        sts_f32(aaddr + eo0, a0);
        sts_f32(aaddr + eo1, a1);
        __syncwarp();
    }

    // ---- epilogue: stage rows in shared, write (B,F,T) with STG.128 ----
    __syncthreads();               // all warps done with union before reuse
    {
        float* stg = &S.stage[wid][0];
        #pragma unroll
        for (int i = 0; i < CH; i++) stg[f_lo + i] = sp[i];
    }
    __syncthreads();
    {
        const int rb = blockIdx.x * WPB;
        const int t0 = rb & (TIME - 1);
        const int bb = rb >> 10;
        float4* ob = reinterpret_cast<float4*>(out + (size_t)bb * N_STFT * TIME + t0);
        #pragma unroll 1
        for (int f = tid; f < N_STFT; f += WPB*32) {
            float4 v = make_float4(S.stage[0][f], S.stage[1][f],
                                   S.stage[2][f], S.stage[3][f]);
            ob[(size_t)f * (TIME/4)] = v;
        }
    }
}

// ---------------- launch ----------------
extern "C" void kernel_launch(void* const* d_in, const int* in_sizes, int n_in,
                              void* d_out, int out_size) {
    const float* mel = nullptr;   // 4*128*1024
    const float* spi = nullptr;   // 4*1024*1025
    const float* fb  = nullptr;   // 1025*128
    for (int i = 0; i < n_in; i++) {
        if      (in_sizes[i] == BATCH * N_MELS * TIME) mel = (const float*)d_in[i];
        else if (in_sizes[i] == ROWS * N_STFT)         spi = (const float*)d_in[i];
        else if (in_sizes[i] == N_STFT * N_MELS)       fb  = (const float*)d_in[i];
    }
    float* out = (float*)d_out;

    build_tables_k<<<FPAD/8, 256>>>(fb);     // warp per frequency
    imel_k<<<ROWS/WPB, WPB*32>>>(mel, spi, out);
}